// round 2
// baseline (speedup 1.0000x reference)
#include <cuda_runtime.h>
#include <cstdint>

#define T_TOK 16384
#define DIN   1280
#define DOUT  3840
#define RANK  16
#define NEXP  6
#define TOPK  3
#define KEXT  112               // 16 shared + 6*16 routed
#define KTOT  (DIN + KEXT)      // 1392

// Scratch (no cudaMalloc allowed)
__device__ __align__(16) float g_P[(size_t)T_TOK * KEXT];  // raw h: [shared(16) | routed(96)]
__device__ __align__(16) float g_G[(size_t)T_TOK * KEXT];  // gated + tf32-rounded A-extension

__device__ __forceinline__ float f2tf32f(float f) {
    uint32_t u;
    asm("cvt.rna.tf32.f32 %0, %1;" : "=r"(u) : "f"(f));
    return __uint_as_float(u);
}

__device__ __forceinline__ void mma_tf32(float c[4],
    uint32_t a0, uint32_t a1, uint32_t a2, uint32_t a3,
    uint32_t b0, uint32_t b1)
{
    asm volatile(
        "mma.sync.aligned.m16n8k8.row.col.f32.tf32.tf32.f32 "
        "{%0,%1,%2,%3}, {%4,%5,%6,%7}, {%8,%9}, {%0,%1,%2,%3};\n"
        : "+f"(c[0]), "+f"(c[1]), "+f"(c[2]), "+f"(c[3])
        : "r"(a0), "r"(a1), "r"(a2), "r"(a3), "r"(b0), "r"(b1));
}

// MODE 0: main GEMM  [T,1392] x [1392,3840]  A = [x | g_G], B = [base_w; shared_w2; routed_w2], +bias -> out
// MODE 1: prep GEMM  [T,1280] x [1280,112]   A = x,        B = [shared_w1 | routed_w1] (gather)  -> g_P
template<int MODE>
__global__ void __launch_bounds__(256) gemm_tf32_k(
    const float* __restrict__ x,
    const float* __restrict__ Bw0,   // MODE0: base_w     MODE1: shared_w1 [1280][16]
    const float* __restrict__ Bw1,   // MODE0: shared_w2  MODE1: routed_w1 [6][1280][16]
    const float* __restrict__ Bw2,   // MODE0: routed_w2  MODE1: unused
    const float* __restrict__ bias,  // MODE0: base_b     MODE1: unused
    float* __restrict__ out)         // MODE0: output     MODE1: unused (writes g_P)
{
    constexpr int NT = (MODE == 0) ? (KTOT / 16) : (DIN / 16);
    __shared__ __align__(16) float As[2][16][136];   // [k][m], pad 136 -> conflict-free frag loads
    __shared__ __align__(16) float Bs[2][16][136];   // [k][n]

    const int tid  = threadIdx.x;
    const int bm   = blockIdx.y * 128;
    const int bn   = blockIdx.x * 128;
    const int warp = tid >> 5;
    const int lane = tid & 31;
    const int wm   = (warp & 1) * 64;    // 2x4 warp grid, 64x32 per warp
    const int wn   = (warp >> 1) * 32;
    const int grp  = lane >> 2;
    const int tig  = lane & 3;

    // global->smem load mapping
    const int arow = tid >> 2;           // 0..63 (two rows: +0, +64)
    const int ak4  = (tid & 3) * 4;      // k offset 0,4,8,12
    const int bk   = tid >> 4;           // 0..15
    const int bn8  = (tid & 15) * 8;     // 0..120

    float acc[4][4][4];
    #pragma unroll
    for (int i = 0; i < 4; i++)
        #pragma unroll
        for (int j = 0; j < 4; j++)
            #pragma unroll
            for (int k = 0; k < 4; k++) acc[i][j][k] = 0.f;

    auto load_tile = [&](int kt, float4* ra, float4* rb) {
        const int k0 = kt * 16;
        #pragma unroll
        for (int i = 0; i < 2; i++) {
            const int m = bm + arow + i * 64;
            const int k = k0 + ak4;
            const float* p;
            if (MODE == 0 && k >= DIN) p = g_G + (size_t)m * KEXT + (k - DIN);
            else                       p = x   + (size_t)m * DIN  + k;
            ra[i] = *reinterpret_cast<const float4*>(p);
        }
        if (MODE == 0) {
            const int k = k0 + bk;
            const float* rowp;
            if (k < DIN)             rowp = Bw0 + (size_t)k * DOUT;
            else if (k < DIN + RANK) rowp = Bw1 + (size_t)(k - DIN) * DOUT;
            else                     rowp = Bw2 + (size_t)(k - DIN - RANK) * DOUT;
            rb[0] = *reinterpret_cast<const float4*>(rowp + bn + bn8);
            rb[1] = *reinterpret_cast<const float4*>(rowp + bn + bn8 + 4);
        } else {
            const int k = k0 + bk;
            float v[8];
            #pragma unroll
            for (int j = 0; j < 8; j++) {
                const int n = bn8 + j;
                float val = 0.f;
                if (n < RANK) {
                    val = Bw0[(size_t)k * RANK + n];
                } else if (n < KEXT) {
                    const int e = (n - RANK) >> 4;
                    const int r = (n - RANK) & 15;
                    val = Bw1[((size_t)e * DIN + k) * RANK + r];
                }
                v[j] = val;
            }
            rb[0] = make_float4(v[0], v[1], v[2], v[3]);
            rb[1] = make_float4(v[4], v[5], v[6], v[7]);
        }
    };

    auto store_tile = [&](int buf, const float4* ra, const float4* rb) {
        #pragma unroll
        for (int i = 0; i < 2; i++) {
            As[buf][ak4 + 0][arow + i * 64] = f2tf32f(ra[i].x);
            As[buf][ak4 + 1][arow + i * 64] = f2tf32f(ra[i].y);
            As[buf][ak4 + 2][arow + i * 64] = f2tf32f(ra[i].z);
            As[buf][ak4 + 3][arow + i * 64] = f2tf32f(ra[i].w);
        }
        float4 c0 = make_float4(f2tf32f(rb[0].x), f2tf32f(rb[0].y), f2tf32f(rb[0].z), f2tf32f(rb[0].w));
        float4 c1 = make_float4(f2tf32f(rb[1].x), f2tf32f(rb[1].y), f2tf32f(rb[1].z), f2tf32f(rb[1].w));
        *reinterpret_cast<float4*>(&Bs[buf][bk][bn8])     = c0;
        *reinterpret_cast<float4*>(&Bs[buf][bk][bn8 + 4]) = c1;
    };

    float4 ra[2], rb[2];
    load_tile(0, ra, rb);
    store_tile(0, ra, rb);
    __syncthreads();

    for (int kt = 0; kt < NT; kt++) {
        const int cur = kt & 1;
        const bool has_next = (kt + 1 < NT);
        float4 na[2], nb[2];
        if (has_next) load_tile(kt + 1, na, nb);

        #pragma unroll
        for (int ks = 0; ks < 2; ks++) {
            const int kb = ks * 8;
            uint32_t af[4][4], bf[4][2];
            #pragma unroll
            for (int mi = 0; mi < 4; mi++) {
                const int m0 = wm + mi * 16;
                af[mi][0] = __float_as_uint(As[cur][kb + tig    ][m0 + grp]);
                af[mi][1] = __float_as_uint(As[cur][kb + tig    ][m0 + grp + 8]);
                af[mi][2] = __float_as_uint(As[cur][kb + tig + 4][m0 + grp]);
                af[mi][3] = __float_as_uint(As[cur][kb + tig + 4][m0 + grp + 8]);
            }
            #pragma unroll
            for (int ni = 0; ni < 4; ni++) {
                const int n0 = wn + ni * 8;
                bf[ni][0] = __float_as_uint(Bs[cur][kb + tig    ][n0 + grp]);
                bf[ni][1] = __float_as_uint(Bs[cur][kb + tig + 4][n0 + grp]);
            }
            #pragma unroll
            for (int mi = 0; mi < 4; mi++)
                #pragma unroll
                for (int ni = 0; ni < 4; ni++)
                    mma_tf32(acc[mi][ni], af[mi][0], af[mi][1], af[mi][2], af[mi][3],
                             bf[ni][0], bf[ni][1]);
        }
        if (has_next) store_tile(cur ^ 1, na, nb);
        __syncthreads();
    }

    #pragma unroll
    for (int mi = 0; mi < 4; mi++) {
        #pragma unroll
        for (int ni = 0; ni < 4; ni++) {
            const int row = bm + wm + mi * 16 + grp;
            const int col = bn + wn + ni * 8 + tig * 2;
            if (MODE == 0) {
                const float b0 = bias[col], b1 = bias[col + 1];
                float2 v0 = make_float2(acc[mi][ni][0] + b0, acc[mi][ni][1] + b1);
                float2 v1 = make_float2(acc[mi][ni][2] + b0, acc[mi][ni][3] + b1);
                *reinterpret_cast<float2*>(out + (size_t)row * DOUT + col)       = v0;
                *reinterpret_cast<float2*>(out + (size_t)(row + 8) * DOUT + col) = v1;
            } else {
                if (col < KEXT) {
                    float2 v0 = make_float2(acc[mi][ni][0], acc[mi][ni][1]);
                    float2 v1 = make_float2(acc[mi][ni][2], acc[mi][ni][3]);
                    *reinterpret_cast<float2*>(g_P + (size_t)row * KEXT + col)       = v0;
                    *reinterpret_cast<float2*>(g_P + (size_t)(row + 8) * KEXT + col) = v1;
                }
            }
        }
    }
}

// One warp per token: exact fp32 router logits, softmax, top-3 gates, build gated
// tf32-rounded A-extension g_G from g_P.
__global__ void __launch_bounds__(256) router_combine_k(
    const float* __restrict__ x,
    const float* __restrict__ rtw,   // [1280][6]
    const float* __restrict__ rtb)   // [6]
{
    const int gwarp = (blockIdx.x * blockDim.x + threadIdx.x) >> 5;
    const int lane  = threadIdx.x & 31;
    if (gwarp >= T_TOK) return;

    const float* xr = x + (size_t)gwarp * DIN;
    float p[NEXP];
    #pragma unroll
    for (int e = 0; e < NEXP; e++) p[e] = 0.f;
    for (int k = lane; k < DIN; k += 32) {
        const float xv = xr[k];
        #pragma unroll
        for (int e = 0; e < NEXP; e++) p[e] += xv * rtw[k * NEXP + e];
    }
    #pragma unroll
    for (int e = 0; e < NEXP; e++) {
        #pragma unroll
        for (int o = 16; o > 0; o >>= 1) p[e] += __shfl_xor_sync(0xffffffffu, p[e], o);
        p[e] += rtb[e];
    }
    // softmax (all lanes redundantly)
    float mx = p[0];
    #pragma unroll
    for (int e = 1; e < NEXP; e++) mx = fmaxf(mx, p[e]);
    float ge[NEXP], s = 0.f;
    #pragma unroll
    for (int e = 0; e < NEXP; e++) { ge[e] = expf(p[e] - mx); s += ge[e]; }
    const float inv = 1.f / s;
    // top-3 -> combine weights
    float cw[NEXP], tmp[NEXP];
    #pragma unroll
    for (int e = 0; e < NEXP; e++) { cw[e] = 0.f; tmp[e] = ge[e]; }
    #pragma unroll
    for (int it = 0; it < TOPK; it++) {
        int bi = 0; float bv = tmp[0];
        #pragma unroll
        for (int e = 1; e < NEXP; e++) if (tmp[e] > bv) { bv = tmp[e]; bi = e; }
        cw[bi] = ge[bi] * inv;
        tmp[bi] = -1.f;
    }
    // gate + tf32-round the extension vector
    for (int j = lane; j < KEXT; j += 32) {
        float v = g_P[(size_t)gwarp * KEXT + j];
        if (j >= RANK) v *= cw[(j - RANK) >> 4];
        g_G[(size_t)gwarp * KEXT + j] = f2tf32f(v);
    }
}

extern "C" void kernel_launch(void* const* d_in, const int* in_sizes, int n_in,
                              void* d_out, int out_size)
{
    const float* x    = (const float*)d_in[0];
    const float* bw   = (const float*)d_in[1];
    const float* bb   = (const float*)d_in[2];
    const float* sw1  = (const float*)d_in[3];
    const float* sw2  = (const float*)d_in[4];
    const float* rw1  = (const float*)d_in[5];
    const float* rw2  = (const float*)d_in[6];
    const float* rtw  = (const float*)d_in[7];
    const float* rtb  = (const float*)d_in[8];
    float* out = (float*)d_out;

    // 1) h vectors (tf32 mma): g_P[t][0:16]=shared h, [16:112]=routed h
    gemm_tf32_k<1><<<dim3(1, T_TOK / 128), 256>>>(x, sw1, rw1, nullptr, nullptr, nullptr);
    // 2) exact-fp32 router + top-3 gating -> g_G (tf32-rounded)
    router_combine_k<<<T_TOK / 8, 256>>>(x, rtw, rtb);
    // 3) fused main GEMM: out = [x|g_G] @ [base_w; shared_w2; routed_w2] + base_b
    gemm_tf32_k<0><<<dim3(DOUT / 128, T_TOK / 128), 256>>>(x, bw, sw2, rw2, bb, out);
}

// round 5
// speedup vs baseline: 1.0935x; 1.0935x over previous
#include <cuda_runtime.h>
#include <cstdint>

#define T_TOK 16384
#define DIN   1280
#define DOUT  3840
#define KEXT  112
#define KTOT  1392
#define NEXP  6
#define TOPK  3
#define STAGES 4
#define SROW  20            // smem row stride in floats (bank-conflict-free, 16B aligned)

// ------- scratch (no cudaMalloc allowed) -------
__device__ __align__(16) float g_X [(size_t)T_TOK * DIN];   // rna-rounded x
__device__ __align__(16) float g_P [(size_t)T_TOK * KEXT];  // raw h vectors
__device__ __align__(16) float g_G [(size_t)T_TOK * KEXT];  // gated + rounded ext
__device__ __align__(16) float g_Bt[(size_t)DOUT * KTOT];   // B^T main (rounded)
__device__ __align__(16) float g_B1[(size_t)128 * DIN];     // B^T prep (rounded, 112 used)

__device__ __forceinline__ float f2tf32f(float f) {
    uint32_t u; asm("cvt.rna.tf32.f32 %0, %1;" : "=r"(u) : "f"(f));
    return __uint_as_float(u);
}
__device__ __forceinline__ uint32_t smem_u32(const void* p) {
    uint32_t a; asm("{ .reg .u64 t; cvta.to.shared.u64 t, %1; cvt.u32.u64 %0, t; }" : "=r"(a) : "l"(p));
    return a;
}
#define CP16(dst, src) asm volatile("cp.async.cg.shared.global [%0], [%1], 16;" :: "r"(dst), "l"(src))
#define CP_COMMIT()    asm volatile("cp.async.commit_group;" ::: "memory")
#define CP_WAIT2()     asm volatile("cp.async.wait_group 2;" ::: "memory")

__device__ __forceinline__ void mma_tf32(float c[4],
    uint32_t a0, uint32_t a1, uint32_t a2, uint32_t a3, uint32_t b0, uint32_t b1)
{
    asm volatile(
        "mma.sync.aligned.m16n8k8.row.col.f32.tf32.tf32.f32 "
        "{%0,%1,%2,%3}, {%4,%5,%6,%7}, {%8,%9}, {%0,%1,%2,%3};\n"
        : "+f"(c[0]), "+f"(c[1]), "+f"(c[2]), "+f"(c[3])
        : "r"(a0), "r"(a1), "r"(a2), "r"(a3), "r"(b0), "r"(b1));
}

// 128x128 CTA tile, 8 warps (2x4), warp tile 64x32, K chunk 16, 4-stage cp.async.
// A chunks < CX come from A1 (stride sA1), >= CX from A2 (stride sA2, rebased).
template<int NK, int CX, bool BIAS>
__global__ void __launch_bounds__(256, 2) gemm_k(
    const float* __restrict__ A1, int sA1,
    const float* __restrict__ A2, int sA2,
    const float* __restrict__ B,  int sB,
    const float* __restrict__ bias,
    float* __restrict__ out, int sOut, int outCols)
{
    extern __shared__ float smf[];
    float* As = smf;                          // [STAGES][128*SROW]
    float* Bs = smf + STAGES * 128 * SROW;
    const uint32_t smA = smem_u32(As);
    const uint32_t smB = smem_u32(Bs);

    const int tid  = threadIdx.x;
    const int bm   = blockIdx.y * 128, bn = blockIdx.x * 128;
    const int warp = tid >> 5, lane = tid & 31;
    const int wm   = (warp & 1) * 64, wn = (warp >> 1) * 32;
    const int grp  = lane >> 2, tig = lane & 3;
    const int lrow = tid >> 1;                // 0..127
    const int fb   = (tid & 1) * 2;           // float4 index base (0 or 2)

    auto issue = [&](int c) {
        const int slot = c & (STAGES - 1);
        const float* asrc = (c < CX)
            ? A1 + (size_t)(bm + lrow) * sA1 + c * 16
            : A2 + (size_t)(bm + lrow) * sA2 + (c - CX) * 16;
        const float* bsrc = B + (size_t)(bn + lrow) * sB + c * 16;
        const uint32_t soff = (uint32_t)(slot * 128 * SROW + lrow * SROW) * 4;
        #pragma unroll
        for (int f = 0; f < 2; f++) {
            CP16(smA + soff + (fb + f) * 16, asrc + (fb + f) * 4);
            CP16(smB + soff + (fb + f) * 16, bsrc + (fb + f) * 4);
        }
    };

    float acc[4][4][4];
    #pragma unroll
    for (int i = 0; i < 4; i++)
        #pragma unroll
        for (int j = 0; j < 4; j++)
            #pragma unroll
            for (int k = 0; k < 4; k++) acc[i][j][k] = 0.f;

    #pragma unroll
    for (int s = 0; s < STAGES - 1; s++) { issue(s); CP_COMMIT(); }

    for (int kc = 0; kc < NK; kc++) {
        CP_WAIT2();
        __syncthreads();
        if (kc + STAGES - 1 < NK) issue(kc + STAGES - 1);
        CP_COMMIT();

        const int slot = kc & (STAGES - 1);
        const float* Ab = As + slot * 128 * SROW;
        const float* Bb = Bs + slot * 128 * SROW;
        #pragma unroll
        for (int ks = 0; ks < 2; ks++) {
            const int kb = ks * 8;
            uint32_t af[4][4], bf[4][2];
            #pragma unroll
            for (int mi = 0; mi < 4; mi++) {
                const int m0 = wm + mi * 16;
                af[mi][0] = __float_as_uint(Ab[(m0 + grp)     * SROW + kb + tig]);
                af[mi][1] = __float_as_uint(Ab[(m0 + grp + 8) * SROW + kb + tig]);
                af[mi][2] = __float_as_uint(Ab[(m0 + grp)     * SROW + kb + tig + 4]);
                af[mi][3] = __float_as_uint(Ab[(m0 + grp + 8) * SROW + kb + tig + 4]);
            }
            #pragma unroll
            for (int ni = 0; ni < 4; ni++) {
                const int n0 = wn + ni * 8;
                bf[ni][0] = __float_as_uint(Bb[(n0 + grp) * SROW + kb + tig]);
                bf[ni][1] = __float_as_uint(Bb[(n0 + grp) * SROW + kb + tig + 4]);
            }
            #pragma unroll
            for (int mi = 0; mi < 4; mi++)
                #pragma unroll
                for (int ni = 0; ni < 4; ni++)
                    mma_tf32(acc[mi][ni], af[mi][0], af[mi][1], af[mi][2], af[mi][3],
                             bf[ni][0], bf[ni][1]);
        }
    }

    #pragma unroll
    for (int mi = 0; mi < 4; mi++) {
        #pragma unroll
        for (int ni = 0; ni < 4; ni++) {
            const int row = bm + wm + mi * 16 + grp;
            const int col = bn + wn + ni * 8 + tig * 2;
            if (col < outCols) {
                float b0 = 0.f, b1 = 0.f;
                if (BIAS) { b0 = bias[col]; b1 = bias[col + 1]; }
                float2 v0 = make_float2(acc[mi][ni][0] + b0, acc[mi][ni][1] + b1);
                float2 v1 = make_float2(acc[mi][ni][2] + b0, acc[mi][ni][3] + b1);
                *reinterpret_cast<float2*>(out + (size_t)row * sOut + col)       = v0;
                *reinterpret_cast<float2*>(out + (size_t)(row + 8) * sOut + col) = v1;
            }
        }
    }
}

// ---- stage B^T main: g_Bt[n][k] rounded, k<1392 ----
__global__ void stage_Bt_k(const float* __restrict__ bw, const float* __restrict__ sw2,
                           const float* __restrict__ rw2)
{
    __shared__ float t[32][33];
    const int k0 = blockIdx.x * 32, n0 = blockIdx.y * 32;
    const int tx = threadIdx.x, ty = threadIdx.y;
    #pragma unroll
    for (int i = 0; i < 4; i++) {
        const int k = k0 + ty + i * 8;
        float v = 0.f;
        if (k < 1280)      v = bw [(size_t)k * DOUT + n0 + tx];
        else if (k < 1296) v = sw2[(size_t)(k - 1280) * DOUT + n0 + tx];
        else if (k < 1392) v = rw2[(size_t)(k - 1296) * DOUT + n0 + tx];
        t[ty + i * 8][tx] = f2tf32f(v);
    }
    __syncthreads();
    const int kk = k0 + tx;
    if (kk < KTOT) {
        #pragma unroll
        for (int i = 0; i < 4; i++)
            g_Bt[(size_t)(n0 + ty + i * 8) * KTOT + kk] = t[tx][ty + i * 8];
    }
}

// ---- stage B^T prep: g_B1[n][k], rows 112..127 zero ----
__global__ void stage_B1_k(const float* __restrict__ sw1, const float* __restrict__ rw1)
{
    const int k = blockIdx.x * 128 + threadIdx.x;
    const int n = blockIdx.y;
    float v = 0.f;
    if (n < 16)       v = sw1[(size_t)k * 16 + n];
    else if (n < 112) v = rw1[(size_t)((n - 16) >> 4) * DIN * 16 + (size_t)k * 16 + ((n - 16) & 15)];
    g_B1[(size_t)n * DIN + k] = f2tf32f(v);
}

// ---- router: exact fp32 logits + top-3; writes g_G (gated, rounded) and g_X (rounded x)
__global__ void __launch_bounds__(256) router_k(
    const float* __restrict__ x, const float* __restrict__ rtw, const float* __restrict__ rtb)
{
    const int gw = (blockIdx.x * blockDim.x + threadIdx.x) >> 5;
    const int lane = threadIdx.x & 31;
    if (gw >= T_TOK) return;
    const float* xr = x + (size_t)gw * DIN;
    float p[NEXP];
    #pragma unroll
    for (int e = 0; e < NEXP; e++) p[e] = 0.f;
    for (int k = lane; k < DIN; k += 32) {
        const float xv = xr[k];
        g_X[(size_t)gw * DIN + k] = f2tf32f(xv);
        #pragma unroll
        for (int e = 0; e < NEXP; e++) p[e] += xv * rtw[k * NEXP + e];
    }
    #pragma unroll
    for (int e = 0; e < NEXP; e++) {
        #pragma unroll
        for (int o = 16; o > 0; o >>= 1) p[e] += __shfl_xor_sync(0xffffffffu, p[e], o);
        p[e] += rtb[e];
    }
    float mx = p[0];
    #pragma unroll
    for (int e = 1; e < NEXP; e++) mx = fmaxf(mx, p[e]);
    float ge[NEXP], ssum = 0.f;
    #pragma unroll
    for (int e = 0; e < NEXP; e++) { ge[e] = expf(p[e] - mx); ssum += ge[e]; }
    const float inv = 1.f / ssum;
    float cw[NEXP], tmp[NEXP];
    #pragma unroll
    for (int e = 0; e < NEXP; e++) { cw[e] = 0.f; tmp[e] = ge[e]; }
    #pragma unroll
    for (int it = 0; it < TOPK; it++) {
        int bi = 0; float bv = tmp[0];
        #pragma unroll
        for (int e = 1; e < NEXP; e++) if (tmp[e] > bv) { bv = tmp[e]; bi = e; }
        cw[bi] = ge[bi] * inv; tmp[bi] = -1.f;
    }
    #pragma unroll
    for (int jj = 0; jj < 4; jj++) {
        const int j = jj * 32 + lane;
        if (j < KEXT) {
            float v = g_P[(size_t)gw * KEXT + j];
            if (j >= 16) v *= cw[(j - 16) >> 4];
            g_G[(size_t)gw * KEXT + j] = f2tf32f(v);
        }
    }
}

extern "C" void kernel_launch(void* const* d_in, const int* in_sizes, int n_in,
                              void* d_out, int out_size)
{
    const float* x   = (const float*)d_in[0];
    const float* bw  = (const float*)d_in[1];
    const float* bb  = (const float*)d_in[2];
    const float* sw1 = (const float*)d_in[3];
    const float* sw2 = (const float*)d_in[4];
    const float* rw1 = (const float*)d_in[5];
    const float* rw2 = (const float*)d_in[6];
    const float* rtw = (const float*)d_in[7];
    const float* rtb = (const float*)d_in[8];
    float* out = (float*)d_out;

    void *pX, *pP, *pG, *pBt, *pB1;
    cudaGetSymbolAddress(&pX,  g_X);
    cudaGetSymbolAddress(&pP,  g_P);
    cudaGetSymbolAddress(&pG,  g_G);
    cudaGetSymbolAddress(&pBt, g_Bt);
    cudaGetSymbolAddress(&pB1, g_B1);

    constexpr int SMSZ = STAGES * 128 * SROW * 2 * 4;   // 81920 B
    cudaFuncSetAttribute(gemm_k<80, 80, false>, cudaFuncAttributeMaxDynamicSharedMemorySize, SMSZ);
    cudaFuncSetAttribute(gemm_k<87, 80, true>,  cudaFuncAttributeMaxDynamicSharedMemorySize, SMSZ);

    // 1) stage rounded operands
    stage_Bt_k<<<dim3(44, DOUT / 32), dim3(32, 8)>>>(bw, sw2, rw2);
    stage_B1_k<<<dim3(DIN / 128, 128), 128>>>(sw1, rw1);
    // 2) prep GEMM: g_P = x @ W1cat  (A raw x, HW tf32 truncation — feeds small terms only)
    gemm_k<80, 80, false><<<dim3(1, T_TOK / 128), 256, SMSZ>>>(
        x, DIN, x, DIN, (const float*)pB1, DIN, nullptr, (float*)pP, KEXT, KEXT);
    // 3) router -> g_G (gated ext), g_X (rounded x)
    router_k<<<T_TOK / 8, 256>>>(x, rtw, rtb);
    // 4) main GEMM: out = [g_X | g_G] @ g_Bt^T + bias
    gemm_k<87, 80, true><<<dim3(DOUT / 128, T_TOK / 128), 256, SMSZ>>>(
        (const float*)pX, DIN, (const float*)pG, KEXT, (const float*)pBt, KTOT, bb, out, DOUT, DOUT);
}

// round 6
// speedup vs baseline: 2.0298x; 1.8562x over previous
#include <cuda_runtime.h>
#include <cuda_fp16.h>
#include <cstdint>

#define T_TOK 16384
#define DIN   1280
#define DOUT  3840
#define KEXTP 128           // padded extension cols (16 shared + 96 routed + 16 zero)
#define KTOT  1408          // 1280 + 128 (cols 1392..1407 zero)
#define NEXP  6
#define TOPK  3
#define STAGES 4
#define CH    32            // K halves per chunk/stage
#define SROWH 40            // smem row stride in halves (conflict-free, 16B-aligned rows)

// ------- scratch (no cudaMalloc allowed) -------
__device__ __align__(16) __half g_X [(size_t)T_TOK * DIN];    // fp16 x
__device__ __align__(16) __half g_G [(size_t)T_TOK * KEXTP];  // gated fp16 ext (pad zero)
__device__ __align__(16) __half g_Bt[(size_t)DOUT * KTOT];    // B^T main fp16 (pad zero)
__device__ __align__(16) __half g_B1[(size_t)128 * DIN];      // B^T prep fp16 (112 real)
__device__ __align__(16) float  g_CW[(size_t)T_TOK * NEXP];   // per-token gate weights

__device__ __forceinline__ uint32_t smem_u32(const void* p) {
    uint32_t a; asm("{ .reg .u64 t; cvta.to.shared.u64 t, %1; cvt.u32.u64 %0, t; }" : "=r"(a) : "l"(p));
    return a;
}
#define CP16(dst, src) asm volatile("cp.async.cg.shared.global [%0], [%1], 16;" :: "r"(dst), "l"(src))
#define CP_COMMIT()    asm volatile("cp.async.commit_group;" ::: "memory")
#define CP_WAIT2()     asm volatile("cp.async.wait_group 2;" ::: "memory")

__device__ __forceinline__ void mma_f16(float c[4],
    uint32_t a0, uint32_t a1, uint32_t a2, uint32_t a3, uint32_t b0, uint32_t b1)
{
    asm volatile(
        "mma.sync.aligned.m16n8k16.row.col.f32.f16.f16.f32 "
        "{%0,%1,%2,%3}, {%4,%5,%6,%7}, {%8,%9}, {%0,%1,%2,%3};\n"
        : "+f"(c[0]), "+f"(c[1]), "+f"(c[2]), "+f"(c[3])
        : "r"(a0), "r"(a1), "r"(a2), "r"(a3), "r"(b0), "r"(b1));
}

// 128x128 CTA tile, 8 warps (2x4 -> warp tile 64x32), K chunk 32 halves, 4-stage cp.async.
// A chunks < CX from A1 (halves, stride sA1), >= CX from A2 (stride sA2, rebased).
// MODE 0: fp32 out + bias.  MODE 1: gated fp16 out to g_G (stride KEXTP).
template<int NK, int CX, int MODE>
__global__ void __launch_bounds__(256, 2) gemm_k(
    const __half* __restrict__ A1, int sA1,
    const __half* __restrict__ A2, int sA2,
    const __half* __restrict__ B,  int sB,
    const float* __restrict__ bias,
    float* __restrict__ outF, int sOut)
{
    extern __shared__ __half smh[];
    __half* As = smh;                            // [STAGES][128*SROWH]
    __half* Bs = smh + STAGES * 128 * SROWH;
    const uint32_t smA = smem_u32(As);
    const uint32_t smB = smem_u32(Bs);

    const int tid  = threadIdx.x;
    const int bm   = blockIdx.y * 128, bn = blockIdx.x * 128;
    const int warp = tid >> 5, lane = tid & 31;
    const int wm   = (warp & 1) * 64, wn = (warp >> 1) * 32;
    const int grp  = lane >> 2, tig = lane & 3;
    const int lrow = tid >> 1;                   // 0..127
    const int fb   = (tid & 1);                  // half-of-row selector

    auto issue = [&](int c) {
        const int slot = c & (STAGES - 1);
        const __half* asrc = (c < CX)
            ? A1 + (size_t)(bm + lrow) * sA1 + c * CH
            : A2 + (size_t)(bm + lrow) * sA2 + (c - CX) * CH;
        const __half* bsrc = B + (size_t)(bn + lrow) * sB + c * CH;
        const uint32_t so = (uint32_t)(slot * 128 * SROWH + lrow * SROWH) * 2 + fb * 32;
        #pragma unroll
        for (int f = 0; f < 2; f++) {
            CP16(smA + so + f * 16, asrc + fb * 16 + f * 8);
            CP16(smB + so + f * 16, bsrc + fb * 16 + f * 8);
        }
    };

    float acc[4][4][4];
    #pragma unroll
    for (int i = 0; i < 4; i++)
        #pragma unroll
        for (int j = 0; j < 4; j++)
            #pragma unroll
            for (int k = 0; k < 4; k++) acc[i][j][k] = 0.f;

    #pragma unroll
    for (int s = 0; s < STAGES - 1; s++) { issue(s); CP_COMMIT(); }

    for (int kc = 0; kc < NK; kc++) {
        CP_WAIT2();
        __syncthreads();
        if (kc + STAGES - 1 < NK) issue(kc + STAGES - 1);
        CP_COMMIT();

        const int slot = kc & (STAGES - 1);
        const __half* Ab = As + slot * 128 * SROWH;
        const __half* Bb = Bs + slot * 128 * SROWH;
        #pragma unroll
        for (int ks = 0; ks < 2; ks++) {
            const int kb = ks * 16;
            uint32_t af[4][4], bf[4][2];
            #pragma unroll
            for (int mi = 0; mi < 4; mi++) {
                const int r0 = (wm + mi * 16 + grp) * SROWH + kb + 2 * tig;
                const int r1 = r0 + 8 * SROWH;
                af[mi][0] = *reinterpret_cast<const uint32_t*>(Ab + r0);
                af[mi][1] = *reinterpret_cast<const uint32_t*>(Ab + r1);
                af[mi][2] = *reinterpret_cast<const uint32_t*>(Ab + r0 + 8);
                af[mi][3] = *reinterpret_cast<const uint32_t*>(Ab + r1 + 8);
            }
            #pragma unroll
            for (int ni = 0; ni < 4; ni++) {
                const int n0 = (wn + ni * 8 + grp) * SROWH + kb + 2 * tig;
                bf[ni][0] = *reinterpret_cast<const uint32_t*>(Bb + n0);
                bf[ni][1] = *reinterpret_cast<const uint32_t*>(Bb + n0 + 8);
            }
            #pragma unroll
            for (int mi = 0; mi < 4; mi++)
                #pragma unroll
                for (int ni = 0; ni < 4; ni++)
                    mma_f16(acc[mi][ni], af[mi][0], af[mi][1], af[mi][2], af[mi][3],
                            bf[ni][0], bf[ni][1]);
        }
    }

    #pragma unroll
    for (int mi = 0; mi < 4; mi++) {
        #pragma unroll
        for (int ni = 0; ni < 4; ni++) {
            const int r0  = bm + wm + mi * 16 + grp;
            const int col = bn + wn + ni * 8 + tig * 2;
            if (MODE == 0) {
                const float b0 = bias[col], b1 = bias[col + 1];
                float2 v0 = make_float2(acc[mi][ni][0] + b0, acc[mi][ni][1] + b1);
                float2 v1 = make_float2(acc[mi][ni][2] + b0, acc[mi][ni][3] + b1);
                *reinterpret_cast<float2*>(outF + (size_t)r0 * sOut + col)       = v0;
                *reinterpret_cast<float2*>(outF + (size_t)(r0 + 8) * sOut + col) = v1;
            } else {
                float g0 = 1.f, g1 = 1.f;
                if (col >= 112)     { g0 = 0.f; g1 = 0.f; }
                else if (col >= 16) {
                    const int e = (col - 16) >> 4;
                    g0 = g_CW[(size_t)r0 * NEXP + e];
                    g1 = g_CW[(size_t)(r0 + 8) * NEXP + e];
                }
                __half2 h0 = __floats2half2_rn(acc[mi][ni][0] * g0, acc[mi][ni][1] * g0);
                __half2 h1 = __floats2half2_rn(acc[mi][ni][2] * g1, acc[mi][ni][3] * g1);
                *reinterpret_cast<__half2*>(g_G + (size_t)r0 * KEXTP + col)       = h0;
                *reinterpret_cast<__half2*>(g_G + (size_t)(r0 + 8) * KEXTP + col) = h1;
            }
        }
    }
}

// ---- stage B^T main: g_Bt[n][k] fp16, k rows 1392..1407 zero ----
__global__ void stage_Bt_k(const float* __restrict__ bw, const float* __restrict__ sw2,
                           const float* __restrict__ rw2)
{
    __shared__ float t[32][33];
    const int k0 = blockIdx.x * 32, n0 = blockIdx.y * 32;
    const int tx = threadIdx.x, ty = threadIdx.y;
    #pragma unroll
    for (int i = 0; i < 4; i++) {
        const int k = k0 + ty + i * 8;
        float v = 0.f;
        if (k < 1280)      v = bw [(size_t)k * DOUT + n0 + tx];
        else if (k < 1296) v = sw2[(size_t)(k - 1280) * DOUT + n0 + tx];
        else if (k < 1392) v = rw2[(size_t)(k - 1296) * DOUT + n0 + tx];
        t[ty + i * 8][tx] = v;
    }
    __syncthreads();
    #pragma unroll
    for (int i = 0; i < 4; i++)
        g_Bt[(size_t)(n0 + ty + i * 8) * KTOT + k0 + tx] = __float2half_rn(t[tx][ty + i * 8]);
}

// ---- stage B^T prep: g_B1[n][k] fp16, rows 112..127 zero ----
__global__ void stage_B1_k(const float* __restrict__ sw1, const float* __restrict__ rw1)
{
    const int k = blockIdx.x * 128 + threadIdx.x;
    const int n = blockIdx.y;
    float v = 0.f;
    if (n < 16)       v = sw1[(size_t)k * 16 + n];
    else if (n < 112) v = rw1[(size_t)((n - 16) >> 4) * DIN * 16 + (size_t)k * 16 + ((n - 16) & 15)];
    g_B1[(size_t)n * DIN + k] = __float2half_rn(v);
}

// ---- router: exact fp32 logits + top-3 -> g_CW; also emits fp16 g_X ----
__global__ void __launch_bounds__(256) router_k(
    const float* __restrict__ x, const float* __restrict__ rtw, const float* __restrict__ rtb)
{
    const int gw = (blockIdx.x * blockDim.x + threadIdx.x) >> 5;
    const int lane = threadIdx.x & 31;
    if (gw >= T_TOK) return;
    const float* xr = x + (size_t)gw * DIN;
    float p[NEXP];
    #pragma unroll
    for (int e = 0; e < NEXP; e++) p[e] = 0.f;
    for (int k = lane; k < DIN; k += 32) {
        const float xv = xr[k];
        g_X[(size_t)gw * DIN + k] = __float2half_rn(xv);
        #pragma unroll
        for (int e = 0; e < NEXP; e++) p[e] += xv * rtw[k * NEXP + e];
    }
    #pragma unroll
    for (int e = 0; e < NEXP; e++) {
        #pragma unroll
        for (int o = 16; o > 0; o >>= 1) p[e] += __shfl_xor_sync(0xffffffffu, p[e], o);
        p[e] += rtb[e];
    }
    float mx = p[0];
    #pragma unroll
    for (int e = 1; e < NEXP; e++) mx = fmaxf(mx, p[e]);
    float ge[NEXP], ssum = 0.f;
    #pragma unroll
    for (int e = 0; e < NEXP; e++) { ge[e] = expf(p[e] - mx); ssum += ge[e]; }
    const float inv = 1.f / ssum;
    float cw[NEXP], tmp[NEXP];
    #pragma unroll
    for (int e = 0; e < NEXP; e++) { cw[e] = 0.f; tmp[e] = ge[e]; }
    #pragma unroll
    for (int it = 0; it < TOPK; it++) {
        int bi = 0; float bv = tmp[0];
        #pragma unroll
        for (int e = 1; e < NEXP; e++) if (tmp[e] > bv) { bv = tmp[e]; bi = e; }
        cw[bi] = ge[bi] * inv; tmp[bi] = -1.f;
    }
    if (lane < NEXP) {
        float v = 0.f;
        #pragma unroll
        for (int e = 0; e < NEXP; e++) if (lane == e) v = cw[e];
        g_CW[(size_t)gw * NEXP + lane] = v;
    }
}

extern "C" void kernel_launch(void* const* d_in, const int* in_sizes, int n_in,
                              void* d_out, int out_size)
{
    const float* x   = (const float*)d_in[0];
    const float* bw  = (const float*)d_in[1];
    const float* bb  = (const float*)d_in[2];
    const float* sw1 = (const float*)d_in[3];
    const float* sw2 = (const float*)d_in[4];
    const float* rw1 = (const float*)d_in[5];
    const float* rw2 = (const float*)d_in[6];
    const float* rtw = (const float*)d_in[7];
    const float* rtb = (const float*)d_in[8];
    float* out = (float*)d_out;

    void *pX, *pG, *pBt, *pB1;
    cudaGetSymbolAddress(&pX,  g_X);
    cudaGetSymbolAddress(&pG,  g_G);
    cudaGetSymbolAddress(&pBt, g_Bt);
    cudaGetSymbolAddress(&pB1, g_B1);

    constexpr int SMSZ = STAGES * 128 * SROWH * 2 * 2;   // 81920 B
    cudaFuncSetAttribute(gemm_k<40, 99, 1>, cudaFuncAttributeMaxDynamicSharedMemorySize, SMSZ);
    cudaFuncSetAttribute(gemm_k<44, 40, 0>, cudaFuncAttributeMaxDynamicSharedMemorySize, SMSZ);

    // 1) stage fp16 operands
    stage_Bt_k<<<dim3(KTOT / 32, DOUT / 32), dim3(32, 8)>>>(bw, sw2, rw2);
    stage_B1_k<<<dim3(DIN / 128, 128), 128>>>(sw1, rw1);
    // 2) router: exact-fp32 gates -> g_CW, and fp16 x -> g_X
    router_k<<<T_TOK / 8, 256>>>(x, rtw, rtb);
    // 3) prep GEMM with fused gating epilogue: g_G = gate(g_X @ W1cat) (fp16)
    gemm_k<40, 99, 1><<<dim3(1, T_TOK / 128), 256, SMSZ>>>(
        (const __half*)pX, DIN, (const __half*)pX, DIN, (const __half*)pB1, DIN,
        nullptr, nullptr, 0);
    // 4) main GEMM: out = [g_X | g_G] @ g_Bt^T + bias
    gemm_k<44, 40, 0><<<dim3(DOUT / 128, T_TOK / 128), 256, SMSZ>>>(
        (const __half*)pX, DIN, (const __half*)pG, KEXTP, (const __half*)pBt, KTOT,
        bb, out, DOUT);
}